// round 16
// baseline (speedup 1.0000x reference)
#include <cuda_runtime.h>
#include <stdint.h>

#define BB 4
#define NN 2000
#define CC 80
#define NCLS 81
#define KPRE 2000
#define MAXOUT 100
#define MAXC 192
#define NHIST 5120
#define HBASE 0x1EA66
#define NSLOT 4
#define SCORE_THR 0.05f
#define IOU_THR 0.5f
#define MAX_RATIO 4.135166556742356f
#define CHK (NHIST / 256)   /* 20 */
#define NRR (MAXC / 32)     /* 6  */

typedef unsigned long long u64;

// ---------------- scratch (device globals; self-cleaning, no allocation) -------
__device__ int g_hist[BB][NHIST];          // zeroed by emit block
__device__ int g_khist[BB][NHIST];         // zeroed by emit block
__device__ u64 g_bslot[BB][NHIST][NSLOT];  // validated by g_hist count (no clean)
__device__ u64 g_kslot[BB][NHIST][NSLOT];  // validated by g_khist count (no clean)
__device__ int g_ccnt[BB][CC];             // zeroed by emit block
__device__ u64 g_ckeys[BB][CC][MAXC];      // only [0,cnt) read
__device__ u64 g_kkeys[BB][2048];          // only [0,kcnt) read (fallback)
__device__ int g_kcnt[BB];                 // zeroed by emit block
__device__ int g_done[BB];                 // zeroed by emit block

__device__ __forceinline__ int bucket_of(unsigned bits) {
    int b = (int)(bits >> 13) - HBASE;
    return min(NHIST - 1, max(0, b));
}

// exact reference fp decode (no FMA contraction)
__device__ __forceinline__ void decode_one(
    u64 key, int img,
    const float* __restrict__ reg, const float* __restrict__ props,
    float h, float w, float maxhw1,
    float4* bx, float4* ob, float* ar)
{
    int flat = (int)(~(unsigned)key);
    int p = flat / CC, c = flat % CC;
    const float* pb = props + ((size_t)img * NN + p) * 4;
    const float* dd = reg + (((size_t)img * NN + p) * CC + c) * 4;

    float dx = __fmul_rn(dd[0], 0.1f);
    float dy = __fmul_rn(dd[1], 0.1f);
    float dw = fminf(fmaxf(__fmul_rn(dd[2], 0.2f), -MAX_RATIO), MAX_RATIO);
    float dh = fminf(fmaxf(__fmul_rn(dd[3], 0.2f), -MAX_RATIO), MAX_RATIO);

    float px = __fmul_rn(__fadd_rn(pb[0], pb[2]), 0.5f);
    float py = __fmul_rn(__fadd_rn(pb[1], pb[3]), 0.5f);
    float pw = __fsub_rn(pb[2], pb[0]);
    float ph = __fsub_rn(pb[3], pb[1]);

    float gx = __fadd_rn(px, __fmul_rn(pw, dx));
    float gy = __fadd_rn(py, __fmul_rn(ph, dy));
    float gw = __fmul_rn(pw, expf(dw));
    float gh = __fmul_rn(ph, expf(dh));
    float hx = __fmul_rn(gw, 0.5f);
    float hy = __fmul_rn(gh, 0.5f);

    float x1 = fminf(fmaxf(__fsub_rn(gx, hx), 0.0f), w);
    float y1 = fminf(fmaxf(__fsub_rn(gy, hy), 0.0f), h);
    float x2 = fminf(fmaxf(__fadd_rn(gx, hx), 0.0f), w);
    float y2 = fminf(fmaxf(__fadd_rn(gy, hy), 0.0f), h);

    *bx = make_float4(x1, y1, x2, y2);
    float off = __fmul_rn((float)c, maxhw1);
    float4 o = make_float4(__fadd_rn(x1, off), __fadd_rn(y1, off),
                           __fadd_rn(x2, off), __fadd_rn(y2, off));
    *ob = o;
    *ar = __fmul_rn(__fsub_rn(o.z, o.x), __fsub_rn(o.w, o.y));
}

__device__ __forceinline__ bool iou_gt(float4 bi, float ai, float4 bj, float aj) {
    float ltx = fmaxf(bi.x, bj.x), lty = fmaxf(bi.y, bj.y);
    float rbx = fminf(bi.z, bj.z), rby = fminf(bi.w, bj.w);
    float wx = fmaxf(__fsub_rn(rbx, ltx), 0.0f);
    float wy = fmaxf(__fsub_rn(rby, lty), 0.0f);
    float inter = __fmul_rn(wx, wy);
    float den = __fadd_rn(__fsub_rn(__fadd_rn(ai, aj), inter), 1e-6f);
    return __fdiv_rn(inter, den) > IOU_THR;
}

// -------- softmax (2 rows/warp) + threshold + per-class scatter + hist+slots ---
__global__ void k_softmax(const float* __restrict__ cls) {
    int gw = (blockIdx.x * blockDim.x + threadIdx.x) >> 5;
    int lane = threadIdx.x & 31;
    if (gw >= BB * NN / 2) return;
    int pr0 = gw * 2;
    int img = pr0 / NN;
    const float* rowA = cls + (size_t)pr0 * NCLS;
    const float* rowB = rowA + NCLS;

    float a0 = rowA[lane], a1 = rowA[lane + 32];
    float a2 = (lane < NCLS - 64) ? rowA[lane + 64] : -1e30f;
    float b0 = rowB[lane], b1 = rowB[lane + 32];
    float b2 = (lane < NCLS - 64) ? rowB[lane + 64] : -1e30f;

    float mA = fmaxf(fmaxf(a0, a1), a2);
    float mB = fmaxf(fmaxf(b0, b1), b2);
    #pragma unroll
    for (int o = 16; o; o >>= 1) {
        mA = fmaxf(mA, __shfl_xor_sync(0xffffffffu, mA, o));
        mB = fmaxf(mB, __shfl_xor_sync(0xffffffffu, mB, o));
    }
    float eA0 = expf(a0 - mA), eA1 = expf(a1 - mA);
    float eA2 = (lane < NCLS - 64) ? expf(a2 - mA) : 0.0f;
    float eB0 = expf(b0 - mB), eB1 = expf(b1 - mB);
    float eB2 = (lane < NCLS - 64) ? expf(b2 - mB) : 0.0f;
    float sA = eA0 + eA1 + eA2;
    float sB = eB0 + eB1 + eB2;
    #pragma unroll
    for (int o = 16; o; o >>= 1) {
        sA += __shfl_xor_sync(0xffffffffu, sA, o);
        sB += __shfl_xor_sync(0xffffffffu, sB, o);
    }
    float sc[6];
    sc[0] = __fdiv_rn(eA0, sA); sc[1] = __fdiv_rn(eA1, sA); sc[2] = __fdiv_rn(eA2, sA);
    sc[3] = __fdiv_rn(eB0, sB); sc[4] = __fdiv_rn(eB1, sB); sc[5] = __fdiv_rn(eB2, sB);

    #pragma unroll
    for (int g = 0; g < 6; g++) {
        int grp = g % 3;
        bool pr = (grp < 2) ? (sc[g] > SCORE_THR)
                            : ((lane < CC - 64) && sc[g] > SCORE_THR);
        if (pr) {
            int p = pr0 + (g / 3) - img * NN;
            int c = lane + grp * 32;
            unsigned sb = __float_as_uint(sc[g]);
            u64 key = ((u64)sb << 32) | (u64)(~(unsigned)(p * CC + c));
            int pos = atomicAdd(&g_ccnt[img][c], 1);
            if (pos < MAXC) {
                g_ckeys[img][c][pos] = key;
                int b = bucket_of(sb);
                int hb = atomicAdd(&g_hist[img][b], 1);
                if (hb < NSLOT) g_bslot[img][b][hb] = key;
            }
        }
    }
}

// -------- NMS: overlapped-prefetch cutoff + warp-per-class NMS + fused emit ----
__global__ void __launch_bounds__(256)
k_nms(const float* __restrict__ reg,
      const float* __restrict__ props,
      const int* __restrict__ hw,
      float* __restrict__ out) {
    __shared__ u64 s_wk[8][MAXC];
    __shared__ u64 s_bk[256];
    __shared__ int s_wsum[8];
    __shared__ int s_total, s_m, s_bcut, s_krem, s_bcnt, s_last, s_over;
    __shared__ u64 s_cut;

    int img = blockIdx.x;
    int t = threadIdx.x;  // 256
    int lane = t & 31, w = t >> 5;
    const unsigned full = 0xffffffffu;
    unsigned lmlt = (1u << lane) - 1u;

    if (t == 0) { s_m = 0; s_bcut = -1; s_cut = 0ULL; s_bcnt = 0; }

    // ---- prefetch this warp's class keys (latency overlaps cutoff phase) ----
    int c = blockIdx.y * 8 + w;
    int cnt = min(g_ccnt[img][c], MAXC);
    u64 kraw[NRR];
    #pragma unroll
    for (int u = 0; u < NRR; u++) {
        int pos = u * 32 + lane;
        kraw[u] = (pos < cnt) ? __ldcg(&g_ckeys[img][c][pos]) : 0ULL;
    }

    // ---- cutoff: ascending int4 histogram chunks, block suffix-count ----
    int hv[CHK];
    {
        const int4* hp = (const int4*)&g_hist[img][t * CHK];
        #pragma unroll
        for (int q = 0; q < CHK / 4; q++) {
            int4 v4 = hp[q];
            hv[q * 4 + 0] = v4.x; hv[q * 4 + 1] = v4.y;
            hv[q * 4 + 2] = v4.z; hv[q * 4 + 3] = v4.w;
        }
    }
    int csum = 0;
    #pragma unroll
    for (int u = 0; u < CHK; u++) csum += hv[u];
    int ws = csum;
    #pragma unroll
    for (int o = 1; o < 32; o <<= 1) {
        int v = __shfl_up_sync(full, ws, o);
        if (lane >= o) ws += v;
    }
    if (lane == 31) s_wsum[w] = ws;
    __syncthreads();
    if (t == 0) {
        int a = 0;
        for (int i = 0; i < 8; i++) { int v = s_wsum[i]; s_wsum[i] = a; a += v; }
        s_total = a;
    }
    __syncthreads();
    int total = s_total;
    int after = total - (s_wsum[w] + ws - csum) - csum;  // keys in buckets above my chunk

    if (total > KPRE) {
        int acc = after;
        #pragma unroll
        for (int u = CHK - 1; u >= 0; u--) {
            int v = hv[u];
            if (acc < KPRE && acc + v >= KPRE) {
                s_bcut = t * CHK + u;
                s_krem = KPRE - acc;
                s_bcnt = v;
            }
            acc += v;
        }
        __syncthreads();
        int bcut = s_bcut, krem = s_krem, bcnt = s_bcnt;
        if (bcnt <= NSLOT) {
            // fast path: all boundary-bucket keys live in slots
            if (t < bcnt) {
                u64 ke = g_bslot[img][bcut][t];
                int r = 0;
                for (int j = 0; j < bcnt; j++)
                    r += (g_bslot[img][bcut][j] > ke);
                if (r == krem - 1) s_cut = ke;   // exact 2000th-largest key
            }
        } else {
            // fallback: scan per-class keys for the boundary bucket (rare)
            for (int cc = w; cc < CC; cc += 8) {
                int cn = min(g_ccnt[img][cc], MAXC);
                for (int pos = lane; pos < cn; pos += 32) {
                    u64 k = g_ckeys[img][cc][pos];
                    if (bucket_of((unsigned)(k >> 32)) == bcut) {
                        int p = atomicAdd(&s_m, 1);
                        if (p < 256) s_bk[p] = k;
                    }
                }
            }
            __syncthreads();
            int m = min(s_m, 256);
            for (int e = t; e < m; e += 256) {
                u64 ke = s_bk[e];
                int r = 0;
                for (int j = 0; j < m; j++) r += (s_bk[j] > ke);
                if (r == krem - 1) s_cut = ke;
            }
        }
    }
    __syncthreads();
    u64 cutoff = s_cut;

    // ---- warp per class: filter (from regs) -> rank-sort -> NMS -> publish ----
    float h = (float)hw[img * 2 + 0];
    float wdt = (float)hw[img * 2 + 1];
    float maxhw1 = __fadd_rn(fmaxf(h, wdt), 1.0f);

    int n = 0;
    #pragma unroll
    for (int u = 0; u < NRR; u++) {
        int pos = u * 32 + lane;
        bool val = (pos < cnt) && (kraw[u] >= cutoff);
        unsigned mk = __ballot_sync(full, val);
        if (val) s_wk[w][n + __popc(mk & lmlt)] = kraw[u];
        n += __popc(mk);
    }
    __syncwarp();
    if (n > 0) {
        int nr = (n + 31) >> 5;
        // rank-sort descending (ranks unique: keys unique)
        u64 kq[NRR];
        int rq[NRR];
        #pragma unroll
        for (int u = 0; u < NRR; u++) {
            int pos = u * 32 + lane;
            kq[u] = (u < nr && pos < n) ? s_wk[w][pos] : 0ULL;
            rq[u] = 0;
        }
        for (int j = 0; j < n; j++) {
            u64 kj = s_wk[w][j];
            #pragma unroll
            for (int u = 0; u < NRR; u++) rq[u] += (kj > kq[u]);
        }
        __syncwarp();
        #pragma unroll
        for (int u = 0; u < NRR; u++) {
            int pos = u * 32 + lane;
            if (u < nr && pos < n) s_wk[w][rq[u]] = kq[u];
        }
        __syncwarp();

        // decode sorted keys into registers
        float4 bb[NRR];
        float aa[NRR];
        unsigned kmask = 0;
        #pragma unroll
        for (int u = 0; u < NRR; u++) {
            bb[u] = make_float4(0, 0, 0, 0);
            aa[u] = 0.0f;
            if (u < nr) {
                int pos = u * 32 + lane;
                if (pos < n) {
                    float4 bx;
                    decode_one(s_wk[w][pos], img, reg, props, h, wdt, maxhw1,
                               &bx, &bb[u], &aa[u]);
                    kmask |= 1u << u;
                }
            }
        }
        // greedy chain in descending order
        #pragma unroll
        for (int u = 0; u < NRR; u++) {
            if (u >= nr) break;
            int ilim = min(n - u * 32, 32);
            for (int li = 0; li < ilim; li++) {
                unsigned am = __ballot_sync(full, (kmask >> u) & 1u);
                if (!((am >> li) & 1u)) continue;
                int i = u * 32 + li;
                float bix = __shfl_sync(full, bb[u].x, li);
                float biy = __shfl_sync(full, bb[u].y, li);
                float biz = __shfl_sync(full, bb[u].z, li);
                float biw = __shfl_sync(full, bb[u].w, li);
                float ai  = __shfl_sync(full, aa[u], li);
                float4 bi = make_float4(bix, biy, biz, biw);
                #pragma unroll
                for (int v = 0; v < NRR; v++) {
                    if (v >= nr) break;
                    int pos = v * 32 + lane;
                    if (pos > i && ((kmask >> v) & 1u)) {
                        if (iou_gt(bi, ai, bb[v], aa[v]))
                            kmask &= ~(1u << v);
                    }
                }
            }
        }
        // publish kept keys: append + kept-hist + per-bucket slots
        #pragma unroll
        for (int u = 0; u < NRR; u++) {
            if (u >= nr) break;
            bool kept = (kmask >> u) & 1u;
            unsigned mk = __ballot_sync(full, kept);
            int tk = __popc(mk);
            int bs = 0;
            if (lane == 0 && tk) bs = atomicAdd(&g_kcnt[img], tk);
            bs = __shfl_sync(full, bs, 0);
            if (kept) {
                u64 k = s_wk[w][u * 32 + lane];
                int idx = bs + __popc(mk & lmlt);
                if (idx < 2048) g_kkeys[img][idx] = k;
                int b = bucket_of((unsigned)(k >> 32));
                int kb = atomicAdd(&g_khist[img][b], 1);
                if (kb < NSLOT) g_kslot[img][b][kb] = k;
            }
        }
    }

    // ---- last-block-done protocol ----
    __syncthreads();
    if (t == 0) {
        __threadfence();
        int old = atomicAdd(&g_done[img], 1);
        s_last = (old == 9) ? 1 : 0;
        s_m = 0; s_bcut = NHIST; s_over = 0;
    }
    __syncthreads();
    if (!s_last) return;
    __threadfence();

    // ---- fused emit: kept-hist boundary -> slot collect (~103 keys) ----
    int kc = min(__ldcg(&g_kcnt[img]), 2048);
    int target = min(MAXOUT, kc);

    int kv[CHK];
    {
        const int4* kp = (const int4*)&g_khist[img][t * CHK];
        #pragma unroll
        for (int q = 0; q < CHK / 4; q++) {
            int4 v4 = __ldcg((int4*)&kp[q]);
            kv[q * 4 + 0] = v4.x; kv[q * 4 + 1] = v4.y;
            kv[q * 4 + 2] = v4.z; kv[q * 4 + 3] = v4.w;
        }
    }
    int csum2 = 0;
    #pragma unroll
    for (int u = 0; u < CHK; u++) csum2 += kv[u];
    int ws2 = csum2;
    #pragma unroll
    for (int o = 1; o < 32; o <<= 1) {
        int v = __shfl_up_sync(full, ws2, o);
        if (lane >= o) ws2 += v;
    }
    if (lane == 31) s_wsum[w] = ws2;
    __syncthreads();
    if (t == 0) {
        int a = 0;
        for (int i = 0; i < 8; i++) { int v = s_wsum[i]; s_wsum[i] = a; a += v; }
        s_total = a;
    }
    __syncthreads();
    int after2 = s_total - (s_wsum[w] + ws2 - csum2) - csum2;
    if (target > 0) {
        int acc = after2;
        #pragma unroll
        for (int u = CHK - 1; u >= 0; u--) {
            int v = kv[u];
            if (acc < target && acc + v >= target)
                s_bcut = t * CHK + u;
            acc += v;
        }
    }
    __syncthreads();
    int bq = s_bcut;

    // overflow check: any bucket >= bq with count > NSLOT?
    bool ov = false;
    #pragma unroll
    for (int u = 0; u < CHK; u++)
        if (t * CHK + u >= bq && kv[u] > NSLOT) ov = true;
    if (ov) s_over = 1;
    __syncthreads();

    if (!s_over) {
        // slot collect: read exactly the keys in buckets >= bq
        #pragma unroll
        for (int u = 0; u < CHK; u++) {
            int b = t * CHK + u;
            int v = kv[u];
            if (b >= bq && v > 0) {
                int p = atomicAdd(&s_m, v);
                for (int j = 0; j < v; j++)
                    if (p + j < 256) s_bk[p + j] = __ldcg(&g_kslot[img][b][j]);
            }
        }
    } else {
        // fallback: scan all kept keys (rare)
        for (int e = t; e < kc; e += 256) {
            u64 k = __ldcg(&g_kkeys[img][e]);
            if (bucket_of((unsigned)(k >> 32)) >= bq) {
                int p = atomicAdd(&s_m, 1);
                if (p < 256) s_bk[p] = k;
            }
        }
    }
    __syncthreads();
    int m = min(s_m, 256);
    for (int e = t; e < m; e += 256) {
        u64 ke = s_bk[e];
        int r = 0;
        for (int j = 0; j < m; j++) r += (s_bk[j] > ke);
        if (r < MAXOUT) {
            float4 bx, ob;
            float ar;
            decode_one(ke, img, reg, props, h, wdt, maxhw1, &bx, &ob, &ar);
            float scv = __uint_as_float((unsigned)(ke >> 32));
            float lb = (float)((int)(~(unsigned)ke) % CC);
            float* bo = out + (size_t)(img * MAXOUT + r) * 4;
            bo[0] = bx.x; bo[1] = bx.y; bo[2] = bx.z; bo[3] = bx.w;
            out[BB * MAXOUT * 4 + img * MAXOUT + r] = scv;
            out[BB * MAXOUT * 5 + img * MAXOUT + r] = lb;
        }
    }
    // pad unfilled slots (kc < 100)
    if (t < MAXOUT && t >= kc) {
        float* bo = out + (size_t)(img * MAXOUT + t) * 4;
        bo[0] = 0.0f; bo[1] = 0.0f; bo[2] = 0.0f; bo[3] = 0.0f;
        out[BB * MAXOUT * 4 + img * MAXOUT + t] = 0.0f;
        out[BB * MAXOUT * 5 + img * MAXOUT + t] = -1.0f;
    }
    // self-clean scratch for next run
    for (int i = t; i < NHIST; i += 256) {
        g_hist[img][i] = 0;
        g_khist[img][i] = 0;
    }
    if (t < CC) g_ccnt[img][t] = 0;
    if (t == 0) { g_kcnt[img] = 0; g_done[img] = 0; }
}

// ---------------- launch (2 kernels) -------------------------------------------
extern "C" void kernel_launch(void* const* d_in, const int* in_sizes, int n_in,
                              void* d_out, int out_size) {
    const float* cls = (const float*)d_in[0];
    const float* reg = (const float*)d_in[1];
    const float* props = (const float*)d_in[2];
    const int* hw = (const int*)d_in[3];
    float* out = (float*)d_out;

    k_softmax<<<(BB * NN / 2 * 32 + 255) / 256, 256>>>(cls);
    dim3 ng(BB, 10);
    k_nms<<<ng, 256>>>(reg, props, hw, out);
}

// round 17
// speedup vs baseline: 1.0699x; 1.0699x over previous
#include <cuda_runtime.h>
#include <stdint.h>

#define BB 4
#define NN 2000
#define CC 80
#define NCLS 81
#define KPRE 2000
#define MAXOUT 100
#define MAXC 192
#define NHIST 5120
#define HBASE 0x1EA66
#define SCORE_THR 0.05f
#define IOU_THR 0.5f
#define MAX_RATIO 4.135166556742356f
#define CHK (NHIST / 256)   /* 20 */
#define NRR (MAXC / 32)     /* 6  */

typedef unsigned long long u64;

// ---------------- scratch (device globals; self-cleaning, no allocation) -------
__device__ int g_hist[BB][NHIST];      // zeroed by emit block
__device__ int g_khist[BB][NHIST];     // zeroed by emit block
__device__ int g_ccnt[BB][CC];         // zeroed by emit block
__device__ u64 g_ckeys[BB][CC][MAXC];  // only [0,cnt) read
__device__ u64 g_kkeys[BB][2048];      // only [0,kcnt) read
__device__ int g_kcnt[BB];             // zeroed by emit block
__device__ int g_done[BB];             // zeroed by emit block

__device__ __forceinline__ int bucket_of(unsigned bits) {
    int b = (int)(bits >> 13) - HBASE;
    return min(NHIST - 1, max(0, b));
}

// exact reference fp decode (no FMA contraction)
__device__ __forceinline__ void decode_one(
    u64 key, int img,
    const float* __restrict__ reg, const float* __restrict__ props,
    float h, float w, float maxhw1,
    float4* bx, float4* ob, float* ar)
{
    int flat = (int)(~(unsigned)key);
    int p = flat / CC, c = flat % CC;
    const float* pb = props + ((size_t)img * NN + p) * 4;
    const float* dd = reg + (((size_t)img * NN + p) * CC + c) * 4;

    float dx = __fmul_rn(dd[0], 0.1f);
    float dy = __fmul_rn(dd[1], 0.1f);
    float dw = fminf(fmaxf(__fmul_rn(dd[2], 0.2f), -MAX_RATIO), MAX_RATIO);
    float dh = fminf(fmaxf(__fmul_rn(dd[3], 0.2f), -MAX_RATIO), MAX_RATIO);

    float px = __fmul_rn(__fadd_rn(pb[0], pb[2]), 0.5f);
    float py = __fmul_rn(__fadd_rn(pb[1], pb[3]), 0.5f);
    float pw = __fsub_rn(pb[2], pb[0]);
    float ph = __fsub_rn(pb[3], pb[1]);

    float gx = __fadd_rn(px, __fmul_rn(pw, dx));
    float gy = __fadd_rn(py, __fmul_rn(ph, dy));
    float gw = __fmul_rn(pw, expf(dw));
    float gh = __fmul_rn(ph, expf(dh));
    float hx = __fmul_rn(gw, 0.5f);
    float hy = __fmul_rn(gh, 0.5f);

    float x1 = fminf(fmaxf(__fsub_rn(gx, hx), 0.0f), w);
    float y1 = fminf(fmaxf(__fsub_rn(gy, hy), 0.0f), h);
    float x2 = fminf(fmaxf(__fadd_rn(gx, hx), 0.0f), w);
    float y2 = fminf(fmaxf(__fadd_rn(gy, hy), 0.0f), h);

    *bx = make_float4(x1, y1, x2, y2);
    float off = __fmul_rn((float)c, maxhw1);
    float4 o = make_float4(__fadd_rn(x1, off), __fadd_rn(y1, off),
                           __fadd_rn(x2, off), __fadd_rn(y2, off));
    *ob = o;
    *ar = __fmul_rn(__fsub_rn(o.z, o.x), __fsub_rn(o.w, o.y));
}

__device__ __forceinline__ bool iou_gt(float4 bi, float ai, float4 bj, float aj) {
    float ltx = fmaxf(bi.x, bj.x), lty = fmaxf(bi.y, bj.y);
    float rbx = fminf(bi.z, bj.z), rby = fminf(bi.w, bj.w);
    float wx = fmaxf(__fsub_rn(rbx, ltx), 0.0f);
    float wy = fmaxf(__fsub_rn(rby, lty), 0.0f);
    float inter = __fmul_rn(wx, wy);
    float den = __fadd_rn(__fsub_rn(__fadd_rn(ai, aj), inter), 1e-6f);
    return __fdiv_rn(inter, den) > IOU_THR;
}

// -------- softmax (2 rows/warp) + threshold + per-class scatter + histogram ----
__global__ void k_softmax(const float* __restrict__ cls) {
    int gw = (blockIdx.x * blockDim.x + threadIdx.x) >> 5;
    int lane = threadIdx.x & 31;
    if (gw >= BB * NN / 2) return;
    int pr0 = gw * 2;
    int img = pr0 / NN;
    const float* rowA = cls + (size_t)pr0 * NCLS;
    const float* rowB = rowA + NCLS;

    float a0 = rowA[lane], a1 = rowA[lane + 32];
    float a2 = (lane < NCLS - 64) ? rowA[lane + 64] : -1e30f;
    float b0 = rowB[lane], b1 = rowB[lane + 32];
    float b2 = (lane < NCLS - 64) ? rowB[lane + 64] : -1e30f;

    float mA = fmaxf(fmaxf(a0, a1), a2);
    float mB = fmaxf(fmaxf(b0, b1), b2);
    #pragma unroll
    for (int o = 16; o; o >>= 1) {
        mA = fmaxf(mA, __shfl_xor_sync(0xffffffffu, mA, o));
        mB = fmaxf(mB, __shfl_xor_sync(0xffffffffu, mB, o));
    }
    float eA0 = expf(a0 - mA), eA1 = expf(a1 - mA);
    float eA2 = (lane < NCLS - 64) ? expf(a2 - mA) : 0.0f;
    float eB0 = expf(b0 - mB), eB1 = expf(b1 - mB);
    float eB2 = (lane < NCLS - 64) ? expf(b2 - mB) : 0.0f;
    float sA = eA0 + eA1 + eA2;
    float sB = eB0 + eB1 + eB2;
    #pragma unroll
    for (int o = 16; o; o >>= 1) {
        sA += __shfl_xor_sync(0xffffffffu, sA, o);
        sB += __shfl_xor_sync(0xffffffffu, sB, o);
    }
    float sc[6];
    sc[0] = __fdiv_rn(eA0, sA); sc[1] = __fdiv_rn(eA1, sA); sc[2] = __fdiv_rn(eA2, sA);
    sc[3] = __fdiv_rn(eB0, sB); sc[4] = __fdiv_rn(eB1, sB); sc[5] = __fdiv_rn(eB2, sB);

    #pragma unroll
    for (int g = 0; g < 6; g++) {
        int grp = g % 3;
        bool pr = (grp < 2) ? (sc[g] > SCORE_THR)
                            : ((lane < CC - 64) && sc[g] > SCORE_THR);
        if (pr) {
            int p = pr0 + (g / 3) - img * NN;
            int c = lane + grp * 32;
            unsigned sb = __float_as_uint(sc[g]);
            u64 key = ((u64)sb << 32) | (u64)(~(unsigned)(p * CC + c));
            int pos = atomicAdd(&g_ccnt[img][c], 1);
            if (pos < MAXC) {
                g_ckeys[img][c][pos] = key;
                atomicAdd(&g_hist[img][bucket_of(sb)], 1);
            }
        }
    }
}

// -------- NMS: in-register cutoff + warp-per-class fixpoint NMS + fused emit ---
__global__ void __launch_bounds__(256)
k_nms(const float* __restrict__ reg,
      const float* __restrict__ props,
      const int* __restrict__ hw,
      float* __restrict__ out) {
    __shared__ int s_cnt[CC];
    __shared__ u64 s_wk[8][MAXC];
    __shared__ u64 s_bk[256];
    __shared__ int s_wsum[8];
    __shared__ int s_total, s_m, s_bcut, s_krem, s_last;
    __shared__ u64 s_cut;

    int img = blockIdx.x;
    int t = threadIdx.x;  // 256
    int lane = t & 31, w = t >> 5;
    const unsigned full = 0xffffffffu;
    unsigned lmlt = (1u << lane) - 1u;

    if (t < CC) s_cnt[t] = min(g_ccnt[img][t], MAXC);
    if (t == 0) { s_m = 0; s_bcut = -1; s_cut = 0ULL; }

    // ---- cutoff: histogram chunks in registers, block suffix-count ----
    int hv[CHK];
    int csum = 0;
    #pragma unroll
    for (int u = 0; u < CHK; u++) {
        hv[u] = g_hist[img][NHIST - 1 - (t * CHK + u)];
        csum += hv[u];
    }
    int ws = csum;
    #pragma unroll
    for (int o = 1; o < 32; o <<= 1) {
        int v = __shfl_up_sync(full, ws, o);
        if (lane >= o) ws += v;
    }
    if (lane == 31) s_wsum[w] = ws;
    __syncthreads();
    if (t == 0) {
        int a = 0;
        for (int i = 0; i < 8; i++) { int v = s_wsum[i]; s_wsum[i] = a; a += v; }
        s_total = a;
    }
    __syncthreads();
    int before = s_wsum[w] + (ws - csum);
    int total = s_total;

    if (total > KPRE) {
        int acc = before;
        #pragma unroll
        for (int u = 0; u < CHK; u++) {
            int v = hv[u];
            if (acc < KPRE && acc + v >= KPRE) {
                s_bcut = NHIST - 1 - (t * CHK + u);
                s_krem = KPRE - acc;
            }
            acc += v;
        }
        __syncthreads();
        int bcut = s_bcut, krem = s_krem;
        for (int cc = w; cc < CC; cc += 8) {
            int cn = s_cnt[cc];
            for (int pos = lane; pos < cn; pos += 32) {
                u64 k = g_ckeys[img][cc][pos];
                if (bucket_of((unsigned)(k >> 32)) == bcut) {
                    int p = atomicAdd(&s_m, 1);
                    if (p < 256) s_bk[p] = k;
                }
            }
        }
        __syncthreads();
        int m = min(s_m, 256);
        for (int e = t; e < m; e += 256) {
            u64 ke = s_bk[e];
            int r = 0;
            for (int j = 0; j < m; j++) r += (s_bk[j] > ke);
            if (r == krem - 1) s_cut = ke;   // exact 2000th-largest key
        }
    }
    __syncthreads();
    u64 cutoff = s_cut;

    // ---- warp per class: filter -> rank-sort -> NMS -> publish ----
    float h = (float)hw[img * 2 + 0];
    float wdt = (float)hw[img * 2 + 1];
    float maxhw1 = __fadd_rn(fmaxf(h, wdt), 1.0f);

    int c = blockIdx.y * 8 + w;
    int cnt = s_cnt[c];
    int n = 0;
    for (int u = 0; u * 32 < cnt; u++) {
        int pos = u * 32 + lane;
        u64 k = (pos < cnt) ? g_ckeys[img][c][pos] : 0ULL;
        bool val = (pos < cnt) && (k >= cutoff);
        unsigned mk = __ballot_sync(full, val);
        if (val) s_wk[w][n + __popc(mk & lmlt)] = k;
        n += __popc(mk);
    }
    __syncwarp();
    if (n > 0 && n <= 32) {
        // ---- FAST PATH: sort by rank, all-pairs mask, ballot fixpoint ----
        bool active = lane < n;
        u64 kq = active ? s_wk[w][lane] : 0ULL;
        int rk = 0;
        for (int j = 0; j < n; j++) rk += (s_wk[w][j] > kq);
        __syncwarp();
        if (active) s_wk[w][rk] = kq;   // descending order
        __syncwarp();
        u64 key = active ? s_wk[w][lane] : 0ULL;
        float4 ob = make_float4(0, 0, 0, 0), bx = make_float4(0, 0, 0, 0);
        float ar = 0.0f;
        if (active)
            decode_one(key, img, reg, props, h, wdt, maxhw1, &bx, &ob, &ar);
        // conflict mask over predecessors (independent iterations: pipelined)
        unsigned m = 0;
        for (int i = 0; i < n; i++) {
            float bix = __shfl_sync(full, ob.x, i);
            float biy = __shfl_sync(full, ob.y, i);
            float biz = __shfl_sync(full, ob.z, i);
            float biw = __shfl_sync(full, ob.w, i);
            float ai  = __shfl_sync(full, ar, i);
            if (active && i < lane &&
                iou_gt(make_float4(bix, biy, biz, biw), ai, ob, ar))
                m |= 1u << i;
        }
        // monotone fixpoint == sequential greedy
        unsigned validb = (n == 32) ? 0xffffffffu : ((1u << n) - 1u);
        unsigned C = 0, D = 0;
        while ((C | D) != validb) {
            bool undec = active && !(((C | D) >> lane) & 1u);
            bool isk = undec && ((m & ~D) == 0u);
            bool isd = undec && ((m & C) != 0u);
            unsigned nk = __ballot_sync(full, isk);
            unsigned nd = __ballot_sync(full, isd);
            C |= nk; D |= nd;
            if (!(nk | nd)) break;   // unreachable (smallest undecided resolves)
        }
        // publish kept keys + kept-histogram
        int tk = __popc(C);
        int bs = 0;
        if (lane == 0 && tk) bs = atomicAdd(&g_kcnt[img], tk);
        bs = __shfl_sync(full, bs, 0);
        if ((C >> lane) & 1u) {
            int idx = bs + __popc(C & lmlt);
            if (idx < 2048) g_kkeys[img][idx] = key;
            atomicAdd(&g_khist[img][bucket_of((unsigned)(key >> 32))], 1);
        }
    } else if (n > 32) {
        // ---- SLOW PATH (n>32): original rank-sort + serial register chain ----
        int nr = (n + 31) >> 5;
        u64 kq[NRR];
        int rq[NRR];
        #pragma unroll
        for (int u = 0; u < NRR; u++) {
            int pos = u * 32 + lane;
            kq[u] = (u < nr && pos < n) ? s_wk[w][pos] : 0ULL;
            rq[u] = 0;
        }
        for (int j = 0; j < n; j++) {
            u64 kj = s_wk[w][j];
            #pragma unroll
            for (int u = 0; u < NRR; u++) rq[u] += (kj > kq[u]);
        }
        __syncwarp();
        #pragma unroll
        for (int u = 0; u < NRR; u++) {
            int pos = u * 32 + lane;
            if (u < nr && pos < n) s_wk[w][rq[u]] = kq[u];
        }
        __syncwarp();

        float4 bb[NRR];
        float aa[NRR];
        unsigned kmask = 0;
        #pragma unroll
        for (int u = 0; u < NRR; u++) {
            bb[u] = make_float4(0, 0, 0, 0);
            aa[u] = 0.0f;
            if (u < nr) {
                int pos = u * 32 + lane;
                if (pos < n) {
                    float4 bx;
                    decode_one(s_wk[w][pos], img, reg, props, h, wdt, maxhw1,
                               &bx, &bb[u], &aa[u]);
                    kmask |= 1u << u;
                }
            }
        }
        #pragma unroll
        for (int u = 0; u < NRR; u++) {
            if (u >= nr) break;
            int ilim = min(n - u * 32, 32);
            for (int li = 0; li < ilim; li++) {
                unsigned am = __ballot_sync(full, (kmask >> u) & 1u);
                if (!((am >> li) & 1u)) continue;
                int i = u * 32 + li;
                float bix = __shfl_sync(full, bb[u].x, li);
                float biy = __shfl_sync(full, bb[u].y, li);
                float biz = __shfl_sync(full, bb[u].z, li);
                float biw = __shfl_sync(full, bb[u].w, li);
                float ai  = __shfl_sync(full, aa[u], li);
                float4 bi = make_float4(bix, biy, biz, biw);
                #pragma unroll
                for (int v = 0; v < NRR; v++) {
                    if (v >= nr) break;
                    int pos = v * 32 + lane;
                    if (pos > i && ((kmask >> v) & 1u)) {
                        if (iou_gt(bi, ai, bb[v], aa[v]))
                            kmask &= ~(1u << v);
                    }
                }
            }
        }
        #pragma unroll
        for (int u = 0; u < NRR; u++) {
            if (u >= nr) break;
            bool kept = (kmask >> u) & 1u;
            unsigned mk = __ballot_sync(full, kept);
            int tk = __popc(mk);
            int bs = 0;
            if (lane == 0 && tk) bs = atomicAdd(&g_kcnt[img], tk);
            bs = __shfl_sync(full, bs, 0);
            if (kept) {
                u64 k = s_wk[w][u * 32 + lane];
                int idx = bs + __popc(mk & lmlt);
                if (idx < 2048) g_kkeys[img][idx] = k;
                atomicAdd(&g_khist[img][bucket_of((unsigned)(k >> 32))], 1);
            }
        }
    }

    // ---- last-block-done protocol ----
    __syncthreads();
    if (t == 0) {
        __threadfence();
        int old = atomicAdd(&g_done[img], 1);
        s_last = (old == 9) ? 1 : 0;
        s_m = 0; s_bcut = NHIST;
    }
    __syncthreads();
    if (!s_last) return;
    __threadfence();

    // ---- fused emit: kept-hist boundary -> rank-compare ~103 keys only ----
    int kc = min(__ldcg(&g_kcnt[img]), 2048);
    int target = min(MAXOUT, kc);

    int kv[CHK];
    int csum2 = 0;
    #pragma unroll
    for (int u = 0; u < CHK; u++) {
        kv[u] = __ldcg(&g_khist[img][NHIST - 1 - (t * CHK + u)]);
        csum2 += kv[u];
    }
    int ws2 = csum2;
    #pragma unroll
    for (int o = 1; o < 32; o <<= 1) {
        int v = __shfl_up_sync(full, ws2, o);
        if (lane >= o) ws2 += v;
    }
    if (lane == 31) s_wsum[w] = ws2;
    __syncthreads();
    if (t == 0) {
        int a = 0;
        for (int i = 0; i < 8; i++) { int v = s_wsum[i]; s_wsum[i] = a; a += v; }
    }
    __syncthreads();
    int before2 = s_wsum[w] + (ws2 - csum2);
    if (target > 0) {
        int acc = before2;
        #pragma unroll
        for (int u = 0; u < CHK; u++) {
            int v = kv[u];
            if (acc < target && acc + v >= target)
                s_bcut = NHIST - 1 - (t * CHK + u);
            acc += v;
        }
    }
    __syncthreads();
    int bq = s_bcut;

    for (int e = t; e < kc; e += 256) {
        u64 k = __ldcg(&g_kkeys[img][e]);
        if (bucket_of((unsigned)(k >> 32)) >= bq) {
            int p = atomicAdd(&s_m, 1);
            if (p < 256) s_bk[p] = k;
        }
    }
    __syncthreads();
    int m = min(s_m, 256);
    for (int e = t; e < m; e += 256) {
        u64 ke = s_bk[e];
        int r = 0;
        for (int j = 0; j < m; j++) r += (s_bk[j] > ke);
        if (r < MAXOUT) {
            float4 bx, ob;
            float ar;
            decode_one(ke, img, reg, props, h, wdt, maxhw1, &bx, &ob, &ar);
            float scv = __uint_as_float((unsigned)(ke >> 32));
            float lb = (float)((int)(~(unsigned)ke) % CC);
            float* bo = out + (size_t)(img * MAXOUT + r) * 4;
            bo[0] = bx.x; bo[1] = bx.y; bo[2] = bx.z; bo[3] = bx.w;
            out[BB * MAXOUT * 4 + img * MAXOUT + r] = scv;
            out[BB * MAXOUT * 5 + img * MAXOUT + r] = lb;
        }
    }
    // pad unfilled slots (kc < 100)
    if (t < MAXOUT && t >= kc) {
        float* bo = out + (size_t)(img * MAXOUT + t) * 4;
        bo[0] = 0.0f; bo[1] = 0.0f; bo[2] = 0.0f; bo[3] = 0.0f;
        out[BB * MAXOUT * 4 + img * MAXOUT + t] = 0.0f;
        out[BB * MAXOUT * 5 + img * MAXOUT + t] = -1.0f;
    }
    // self-clean scratch for next run
    for (int i = t; i < NHIST; i += 256) {
        g_hist[img][i] = 0;
        g_khist[img][i] = 0;
    }
    if (t < CC) g_ccnt[img][t] = 0;
    if (t == 0) { g_kcnt[img] = 0; g_done[img] = 0; }
}

// ---------------- launch (2 kernels) -------------------------------------------
extern "C" void kernel_launch(void* const* d_in, const int* in_sizes, int n_in,
                              void* d_out, int out_size) {
    const float* cls = (const float*)d_in[0];
    const float* reg = (const float*)d_in[1];
    const float* props = (const float*)d_in[2];
    const int* hw = (const int*)d_in[3];
    float* out = (float*)d_out;

    k_softmax<<<(BB * NN / 2 * 32 + 255) / 256, 256>>>(cls);
    dim3 ng(BB, 10);
    k_nms<<<ng, 256>>>(reg, props, hw, out);
}